// round 2
// baseline (speedup 1.0000x reference)
#include <cuda_runtime.h>
#include <cstdint>

#define D_MODEL 1024
#define NUM_HEADS 16
#define DEPTH 64
#define BATCH 2
#define SEQ 2048
#define MTOT (BATCH * SEQ)            // 4096 rows
#define OUT_ELEMS ((long long)BATCH * SEQ * D_MODEL)          // 4,194,304
#define ATTN_ELEMS ((long long)BATCH * NUM_HEADS * SEQ * SEQ) // 134,217,728

// Scratch (no allocations allowed) — 4 x 16 MB
__device__ float g_Q[MTOT * D_MODEL];
__device__ float g_K[MTOT * D_MODEL];
__device__ float g_V[MTOT * D_MODEL];
__device__ float g_ctx[MTOT * D_MODEL];

// ---------------------------------------------------------------------------
// Tiled fp32 GEMM: C[M,N] = A[M,K] @ W[K,N] + bias[N]
// 128x128 tile, TK=8, 256 threads, 8x8 accum per thread.
// ---------------------------------------------------------------------------
#define GTK 8
__global__ __launch_bounds__(256) void gemm_bias_kernel(
    const float* __restrict__ A, const float* __restrict__ W,
    const float* __restrict__ bias, float* __restrict__ C,
    int M, int N, int K)
{
    __shared__ float As[GTK][132];   // padded, stored transposed
    __shared__ float Bs[GTK][128];

    const int tid = threadIdx.x;
    const int bm = blockIdx.y * 128;
    const int bn = blockIdx.x * 128;
    const int tx = tid & 15;         // n direction
    const int ty = tid >> 4;         // m direction

    float acc[8][8];
#pragma unroll
    for (int i = 0; i < 8; i++)
#pragma unroll
        for (int j = 0; j < 8; j++) acc[i][j] = 0.f;

    const int ar = tid >> 1;              // 0..127 (A row within tile)
    const int akc = (tid & 1) * 4;        // 0 or 4 (A k offset)
    const int bkr = tid >> 5;             // 0..7   (B k row)
    const int bnc = (tid & 31) * 4;       // 0..124 (B n offset)

    for (int k0 = 0; k0 < K; k0 += GTK) {
        // A tile: 128 rows x 8 k  (one float4 per thread)
        {
            float4 v = *reinterpret_cast<const float4*>(
                A + (size_t)(bm + ar) * K + k0 + akc);
            As[akc + 0][ar] = v.x;
            As[akc + 1][ar] = v.y;
            As[akc + 2][ar] = v.z;
            As[akc + 3][ar] = v.w;
        }
        // B tile: 8 k rows x 128 n (one float4 per thread, fully coalesced)
        {
            float4 v = *reinterpret_cast<const float4*>(
                W + (size_t)(k0 + bkr) * N + bn + bnc);
            *reinterpret_cast<float4*>(&Bs[bkr][bnc]) = v;
        }
        __syncthreads();

#pragma unroll
        for (int kk = 0; kk < GTK; kk++) {
            float a[8], b[8];
#pragma unroll
            for (int i = 0; i < 8; i++) a[i] = As[kk][ty * 8 + i];
#pragma unroll
            for (int j = 0; j < 8; j++) b[j] = Bs[kk][tx * 8 + j];
#pragma unroll
            for (int i = 0; i < 8; i++)
#pragma unroll
                for (int j = 0; j < 8; j++) acc[i][j] += a[i] * b[j];
        }
        __syncthreads();
    }

#pragma unroll
    for (int i = 0; i < 8; i++) {
        int m = bm + ty * 8 + i;
#pragma unroll
        for (int j = 0; j < 8; j += 4) {
            int n = bn + tx * 8 + j;
            float4 o;
            o.x = acc[i][j + 0] + bias[n + 0];
            o.y = acc[i][j + 1] + bias[n + 1];
            o.z = acc[i][j + 2] + bias[n + 2];
            o.w = acc[i][j + 3] + bias[n + 3];
            *reinterpret_cast<float4*>(C + (size_t)m * N + n) = o;
        }
    }
}

// ---------------------------------------------------------------------------
// Causal attention, one block per (b, h, q-row). 128 threads.
// Computes logits (k <= q), exact softmax, writes attn row (zeros beyond q),
// and ctx[b,q,h*64+d].
// ---------------------------------------------------------------------------
#define KC 128
__global__ __launch_bounds__(128) void attn_kernel(
    const float* __restrict__ Qp, const float* __restrict__ Kp,
    const float* __restrict__ Vp, float* __restrict__ attn,
    float* __restrict__ ctx, int write_attn)
{
    __shared__ float qv[DEPTH];
    __shared__ float Ks[KC][DEPTH + 1];   // stride 65: conflict-free both ways
    __shared__ float lg[SEQ];
    __shared__ float red[4];
    __shared__ float csum[2][DEPTH];

    const int t = threadIdx.x;
    const int q = blockIdx.x;
    const int h = blockIdx.y;
    const int b = blockIdx.z;

    const size_t rowQ = ((size_t)b * SEQ + q) * D_MODEL + h * DEPTH;
    if (t < DEPTH) qv[t] = Qp[rowQ + t];
    __syncthreads();

    const int nk = q + 1;
    const int nch = (nk + KC - 1) / KC;

    // ---- Pass 1: logits ----
    for (int c = 0; c < nch; c++) {
        const int kbase = c * KC;
        // load K chunk [128 x 64] (float4 per slot, coalesced)
#pragma unroll
        for (int i = 0; i < 16; i++) {
            int f4 = t + i * 128;
            int kr = f4 >> 4;
            int d4 = (f4 & 15) * 4;
            float4 v = *reinterpret_cast<const float4*>(
                Kp + ((size_t)b * SEQ + kbase + kr) * D_MODEL + h * DEPTH + d4);
            Ks[kr][d4 + 0] = v.x;
            Ks[kr][d4 + 1] = v.y;
            Ks[kr][d4 + 2] = v.z;
            Ks[kr][d4 + 3] = v.w;
        }
        __syncthreads();
        int k = kbase + t;
        if (k < nk) {
            float acc = 0.f;
#pragma unroll
            for (int d = 0; d < DEPTH; d++) acc += qv[d] * Ks[t][d];
            lg[k] = acc * 0.125f;   // 1/sqrt(64)
        }
        __syncthreads();
    }

    // ---- max reduce ----
    float mx = -1e30f;
    for (int k = t; k < nk; k += 128) mx = fmaxf(mx, lg[k]);
#pragma unroll
    for (int o = 16; o; o >>= 1) mx = fmaxf(mx, __shfl_xor_sync(0xFFFFFFFFu, mx, o));
    if ((t & 31) == 0) red[t >> 5] = mx;
    __syncthreads();
    mx = fmaxf(fmaxf(red[0], red[1]), fmaxf(red[2], red[3]));
    __syncthreads();

    // ---- exp + sum ----
    float sm = 0.f;
    for (int k = t; k < nk; k += 128) {
        float e = __expf(lg[k] - mx);
        lg[k] = e;
        sm += e;
    }
#pragma unroll
    for (int o = 16; o; o >>= 1) sm += __shfl_xor_sync(0xFFFFFFFFu, sm, o);
    if ((t & 31) == 0) red[t >> 5] = sm;
    __syncthreads();
    sm = red[0] + red[1] + red[2] + red[3];
    const float inv = 1.0f / sm;

    // ---- normalize + write attn row ----
    const size_t arow = (((size_t)b * NUM_HEADS + h) * SEQ + q) * SEQ;
    for (int k = t; k < SEQ; k += 128) {
        float p = (k < nk) ? lg[k] * inv : 0.f;
        if (k < nk) lg[k] = p;
        if (write_attn) attn[arow + k] = p;
    }
    __syncthreads();

    // ---- ctx = p @ V ----
    const int d = t & 63;
    const int half = t >> 6;
    float acc = 0.f;
    for (int c = 0; c < nch; c++) {
        const int kbase = c * KC;
#pragma unroll
        for (int i = 0; i < 16; i++) {
            int f4 = t + i * 128;
            int kr = f4 >> 4;
            int d4 = (f4 & 15) * 4;
            float4 v = *reinterpret_cast<const float4*>(
                Vp + ((size_t)b * SEQ + kbase + kr) * D_MODEL + h * DEPTH + d4);
            Ks[kr][d4 + 0] = v.x;
            Ks[kr][d4 + 1] = v.y;
            Ks[kr][d4 + 2] = v.z;
            Ks[kr][d4 + 3] = v.w;
        }
        __syncthreads();
        int lim = nk - kbase;
        if (lim > KC) lim = KC;
        for (int kk = half; kk < lim; kk += 2)
            acc += lg[kbase + kk] * Ks[kk][d];
        __syncthreads();
    }
    csum[half][d] = acc;
    __syncthreads();
    if (t < DEPTH) ctx[rowQ + t] = csum[0][t] + csum[1][t];
}

// ---------------------------------------------------------------------------
extern "C" void kernel_launch(void* const* d_in, const int* in_sizes, int n_in,
                              void* d_out, int out_size)
{
    const float* q  = (const float*)d_in[0];
    const float* k  = (const float*)d_in[1];
    const float* v  = (const float*)d_in[2];
    // d_in[3] is the mask — causal structure applied analytically.
    const float* wq = (const float*)d_in[4];
    const float* bq = (const float*)d_in[5];
    const float* wk = (const float*)d_in[6];
    const float* bk = (const float*)d_in[7];
    const float* wv = (const float*)d_in[8];
    const float* bv = (const float*)d_in[9];
    const float* wo = (const float*)d_in[10];
    const float* bo = (const float*)d_in[11];

    float* out = (float*)d_out;
    float* attn = nullptr;
    int write_attn = 0;
    if ((long long)out_size >= OUT_ELEMS + ATTN_ELEMS) {
        attn = out + OUT_ELEMS;
        write_attn = 1;
    }

    float *Qs, *Ks, *Vs, *Cs;
    cudaGetSymbolAddress((void**)&Qs, g_Q);
    cudaGetSymbolAddress((void**)&Ks, g_K);
    cudaGetSymbolAddress((void**)&Vs, g_V);
    cudaGetSymbolAddress((void**)&Cs, g_ctx);

    dim3 ggrid(D_MODEL / 128, MTOT / 128);   // (8, 32)
    gemm_bias_kernel<<<ggrid, 256>>>(q, wq, bq, Qs, MTOT, D_MODEL, D_MODEL);
    gemm_bias_kernel<<<ggrid, 256>>>(k, wk, bk, Ks, MTOT, D_MODEL, D_MODEL);
    gemm_bias_kernel<<<ggrid, 256>>>(v, wv, bv, Vs, MTOT, D_MODEL, D_MODEL);

    attn_kernel<<<dim3(SEQ, NUM_HEADS, BATCH), 128>>>(Qs, Ks, Vs, attn, Cs, write_attn);

    gemm_bias_kernel<<<ggrid, 256>>>(Cs, wo, bo, out, MTOT, D_MODEL, D_MODEL);
}

// round 3
// speedup vs baseline: 3.5531x; 3.5531x over previous
#include <cuda_runtime.h>
#include <cstdint>

#define D_MODEL 1024
#define NUM_HEADS 16
#define DEPTH 64
#define BATCH 2
#define SEQ 2048
#define MTOT (BATCH * SEQ)            // 4096 rows
#define OUT_ELEMS ((long long)BATCH * SEQ * D_MODEL)          // 4,194,304
#define ATTN_ELEMS ((long long)BATCH * NUM_HEADS * SEQ * SEQ) // 134,217,728

// Scratch (no allocations allowed) — 4 x 16 MB
__device__ float g_Q[MTOT * D_MODEL];
__device__ float g_K[MTOT * D_MODEL];
__device__ float g_V[MTOT * D_MODEL];
__device__ float g_ctx[MTOT * D_MODEL];

// ---------------------------------------------------------------------------
// Tiled fp32 GEMM: C[M,N] = A[M,K] @ W[K,N] + bias[N]
// 128x128 tile, TK=8, 256 threads, 8x8 accum per thread.
// ---------------------------------------------------------------------------
#define GTK 8
__global__ __launch_bounds__(256) void gemm_bias_kernel(
    const float* __restrict__ A, const float* __restrict__ W,
    const float* __restrict__ bias, float* __restrict__ C,
    int M, int N, int K)
{
    __shared__ float As[GTK][132];   // padded, stored transposed
    __shared__ float Bs[GTK][128];

    const int tid = threadIdx.x;
    const int bm = blockIdx.y * 128;
    const int bn = blockIdx.x * 128;
    const int tx = tid & 15;         // n direction
    const int ty = tid >> 4;         // m direction

    float acc[8][8];
#pragma unroll
    for (int i = 0; i < 8; i++)
#pragma unroll
        for (int j = 0; j < 8; j++) acc[i][j] = 0.f;

    const int ar = tid >> 1;              // 0..127 (A row within tile)
    const int akc = (tid & 1) * 4;        // 0 or 4 (A k offset)
    const int bkr = tid >> 5;             // 0..7   (B k row)
    const int bnc = (tid & 31) * 4;       // 0..124 (B n offset)

    for (int k0 = 0; k0 < K; k0 += GTK) {
        {
            float4 v = *reinterpret_cast<const float4*>(
                A + (size_t)(bm + ar) * K + k0 + akc);
            As[akc + 0][ar] = v.x;
            As[akc + 1][ar] = v.y;
            As[akc + 2][ar] = v.z;
            As[akc + 3][ar] = v.w;
        }
        {
            float4 v = *reinterpret_cast<const float4*>(
                W + (size_t)(k0 + bkr) * N + bn + bnc);
            *reinterpret_cast<float4*>(&Bs[bkr][bnc]) = v;
        }
        __syncthreads();

#pragma unroll
        for (int kk = 0; kk < GTK; kk++) {
            float a[8], b[8];
#pragma unroll
            for (int i = 0; i < 8; i++) a[i] = As[kk][ty * 8 + i];
#pragma unroll
            for (int j = 0; j < 8; j++) b[j] = Bs[kk][tx * 8 + j];
#pragma unroll
            for (int i = 0; i < 8; i++)
#pragma unroll
                for (int j = 0; j < 8; j++) acc[i][j] += a[i] * b[j];
        }
        __syncthreads();
    }

#pragma unroll
    for (int i = 0; i < 8; i++) {
        int m = bm + ty * 8 + i;
#pragma unroll
        for (int j = 0; j < 8; j += 4) {
            int n = bn + tx * 8 + j;
            float4 o;
            o.x = acc[i][j + 0] + bias[n + 0];
            o.y = acc[i][j + 1] + bias[n + 1];
            o.z = acc[i][j + 2] + bias[n + 2];
            o.w = acc[i][j + 3] + bias[n + 3];
            *reinterpret_cast<float4*>(C + (size_t)m * N + n) = o;
        }
    }
}

// ---------------------------------------------------------------------------
// Register-tiled causal attention. One block per (b, h, 64-row q-tile).
// 128 threads; each thread owns an 8x4 fragment of S / P / ctx.
// Writes unnormalized exp(logit) to attn, accumulates row sums in regs,
// rescales its own attn rows (and zeros the masked region) in an epilogue.
// ---------------------------------------------------------------------------
__global__ __launch_bounds__(128, 4) void attn_pass1(
    const float* __restrict__ Qp, const float* __restrict__ Kp,
    const float* __restrict__ Vp, float* __restrict__ attn,
    float* __restrict__ ctx)
{
    __shared__ float Qs[64][65];
    __shared__ float KVs[64][65];
    __shared__ float Ps[64][65];
    __shared__ float invs[64];

    const int tid   = threadIdx.x;
    const int qt    = (int)gridDim.x - 1 - (int)blockIdx.x;   // largest tile first
    const int h     = blockIdx.y & (NUM_HEADS - 1);
    const int b     = blockIdx.y >> 4;
    const int qbase = qt * 64;

    const int tx = tid & 15;
    const int ty = tid >> 4;            // 0..7
    const int r0 = ty * 8;
    const int n0 = tx * 4;

    const size_t qkvBase  = (size_t)b * SEQ * D_MODEL + (size_t)h * DEPTH;
    const size_t attnRow0 = (((size_t)b * NUM_HEADS + h) * SEQ + qbase) * SEQ;

    // Load Q tile [64 rows][64 d]
#pragma unroll
    for (int it = 0; it < 8; it++) {
        int idx = tid + it * 128;
        int r  = idx >> 4;
        int d4 = (idx & 15) * 4;
        float4 v = *reinterpret_cast<const float4*>(
            Qp + qkvBase + (size_t)(qbase + r) * D_MODEL + d4);
        Qs[r][d4 + 0] = v.x; Qs[r][d4 + 1] = v.y;
        Qs[r][d4 + 2] = v.z; Qs[r][d4 + 3] = v.w;
    }

    float ctxa[8][4];
    float rpart[8];
#pragma unroll
    for (int i = 0; i < 8; i++) {
        rpart[i] = 0.f;
#pragma unroll
        for (int j = 0; j < 4; j++) ctxa[i][j] = 0.f;
    }

    __syncthreads();

    for (int c = 0; c <= qt; c++) {
        const int kbase = c * 64;

        // Load K chunk [64 rows][64 d]
#pragma unroll
        for (int it = 0; it < 8; it++) {
            int idx = tid + it * 128;
            int r  = idx >> 4;
            int d4 = (idx & 15) * 4;
            float4 v = *reinterpret_cast<const float4*>(
                Kp + qkvBase + (size_t)(kbase + r) * D_MODEL + d4);
            KVs[r][d4 + 0] = v.x; KVs[r][d4 + 1] = v.y;
            KVs[r][d4 + 2] = v.z; KVs[r][d4 + 3] = v.w;
        }
        __syncthreads();

        // S = Q @ K^T  (8x4 fragment per thread)
        float s[8][4];
#pragma unroll
        for (int i = 0; i < 8; i++)
#pragma unroll
            for (int j = 0; j < 4; j++) s[i][j] = 0.f;

#pragma unroll 4
        for (int k = 0; k < 64; k++) {
            float a[8], bb[4];
#pragma unroll
            for (int i = 0; i < 8; i++) a[i] = Qs[r0 + i][k];
#pragma unroll
            for (int j = 0; j < 4; j++) bb[j] = KVs[n0 + j][k];
#pragma unroll
            for (int i = 0; i < 8; i++)
#pragma unroll
                for (int j = 0; j < 4; j++) s[i][j] += a[i] * bb[j];
        }

        // P = exp(S/8) with causal mask on the diagonal tile.
        const bool diag = (c == qt);
#pragma unroll
        for (int i = 0; i < 8; i++) {
            float p[4];
#pragma unroll
            for (int j = 0; j < 4; j++) {
                float e = __expf(s[i][j] * 0.125f);
                if (diag && (n0 + j) > (r0 + i)) e = 0.f;
                p[j] = e;
                rpart[i] += e;
                Ps[r0 + i][n0 + j] = e;
            }
            if (attn) {
                float4 pv; pv.x = p[0]; pv.y = p[1]; pv.z = p[2]; pv.w = p[3];
                *reinterpret_cast<float4*>(
                    attn + attnRow0 + (size_t)(r0 + i) * SEQ + kbase + n0) = pv;
            }
        }
        __syncthreads();   // done reading K, Ps fully written

        // Load V chunk [64 k][64 d]
#pragma unroll
        for (int it = 0; it < 8; it++) {
            int idx = tid + it * 128;
            int r  = idx >> 4;
            int d4 = (idx & 15) * 4;
            float4 v = *reinterpret_cast<const float4*>(
                Vp + qkvBase + (size_t)(kbase + r) * D_MODEL + d4);
            KVs[r][d4 + 0] = v.x; KVs[r][d4 + 1] = v.y;
            KVs[r][d4 + 2] = v.z; KVs[r][d4 + 3] = v.w;
        }
        __syncthreads();

        // ctx += P @ V
#pragma unroll 4
        for (int k = 0; k < 64; k++) {
            float a[8], bb[4];
#pragma unroll
            for (int i = 0; i < 8; i++) a[i] = Ps[r0 + i][k];
#pragma unroll
            for (int j = 0; j < 4; j++) bb[j] = KVs[k][n0 + j];
#pragma unroll
            for (int i = 0; i < 8; i++)
#pragma unroll
                for (int j = 0; j < 4; j++) ctxa[i][j] += a[i] * bb[j];
        }
        __syncthreads();   // before KVs/Ps reuse next chunk
    }

    // Reduce row sums across the 16 thread-columns (reuse Ps)
#pragma unroll
    for (int i = 0; i < 8; i++) Ps[r0 + i][tx] = rpart[i];
    __syncthreads();
    if (tid < 64) {
        float sm = 0.f;
#pragma unroll
        for (int x = 0; x < 16; x++) sm += Ps[tid][x];
        invs[tid] = 1.0f / sm;
    }
    __syncthreads();

    // Write normalized ctx: ctx[b, q, h*64 + d]
#pragma unroll
    for (int i = 0; i < 8; i++) {
        float inv = invs[r0 + i];
        float4 v;
        v.x = ctxa[i][0] * inv; v.y = ctxa[i][1] * inv;
        v.z = ctxa[i][2] * inv; v.w = ctxa[i][3] * inv;
        *reinterpret_cast<float4*>(
            ctx + qkvBase + (size_t)(qbase + r0 + i) * D_MODEL + n0) = v;
    }

    // Epilogue: rescale this block's attn rows; zero the masked region.
    if (attn) {
        for (int c = 0; c < SEQ / 64; c++) {
            const int kbase = c * 64;
            if (c <= qt) {
#pragma unroll
                for (int it = 0; it < 8; it++) {
                    int idx = tid + it * 128;
                    int r  = idx >> 4;
                    int d4 = (idx & 15) * 4;
                    float inv = invs[r];
                    float4* p = reinterpret_cast<float4*>(
                        attn + attnRow0 + (size_t)r * SEQ + kbase + d4);
                    float4 v = *p;
                    v.x *= inv; v.y *= inv; v.z *= inv; v.w *= inv;
                    *p = v;
                }
            } else {
                const float4 z = {0.f, 0.f, 0.f, 0.f};
#pragma unroll
                for (int it = 0; it < 8; it++) {
                    int idx = tid + it * 128;
                    int r  = idx >> 4;
                    int d4 = (idx & 15) * 4;
                    *reinterpret_cast<float4*>(
                        attn + attnRow0 + (size_t)r * SEQ + kbase + d4) = z;
                }
            }
        }
    }
}

// ---------------------------------------------------------------------------
extern "C" void kernel_launch(void* const* d_in, const int* in_sizes, int n_in,
                              void* d_out, int out_size)
{
    const float* q  = (const float*)d_in[0];
    const float* k  = (const float*)d_in[1];
    const float* v  = (const float*)d_in[2];
    // d_in[3] is the mask — causal structure applied analytically.
    const float* wq = (const float*)d_in[4];
    const float* bq = (const float*)d_in[5];
    const float* wk = (const float*)d_in[6];
    const float* bk = (const float*)d_in[7];
    const float* wv = (const float*)d_in[8];
    const float* bv = (const float*)d_in[9];
    const float* wo = (const float*)d_in[10];
    const float* bo = (const float*)d_in[11];

    float* out = (float*)d_out;
    float* attn = nullptr;
    if ((long long)out_size >= OUT_ELEMS + ATTN_ELEMS) {
        attn = out + OUT_ELEMS;
    }

    float *Qs, *Ks, *Vs, *Cs;
    cudaGetSymbolAddress((void**)&Qs, g_Q);
    cudaGetSymbolAddress((void**)&Ks, g_K);
    cudaGetSymbolAddress((void**)&Vs, g_V);
    cudaGetSymbolAddress((void**)&Cs, g_ctx);

    dim3 ggrid(D_MODEL / 128, MTOT / 128);   // (8, 32)
    gemm_bias_kernel<<<ggrid, 256>>>(q, wq, bq, Qs, MTOT, D_MODEL, D_MODEL);
    gemm_bias_kernel<<<ggrid, 256>>>(k, wk, bk, Ks, MTOT, D_MODEL, D_MODEL);
    gemm_bias_kernel<<<ggrid, 256>>>(v, wv, bv, Vs, MTOT, D_MODEL, D_MODEL);

    attn_pass1<<<dim3(SEQ / 64, BATCH * NUM_HEADS), 128>>>(Qs, Ks, Vs, attn, Cs);

    gemm_bias_kernel<<<ggrid, 256>>>(Cs, wo, bo, out, MTOT, D_MODEL, D_MODEL);
}

// round 5
// speedup vs baseline: 3.5709x; 1.0050x over previous
#include <cuda_runtime.h>
#include <cstdint>

#define D_MODEL 1024
#define NUM_HEADS 16
#define DEPTH 64
#define BATCH 2
#define SEQ 2048
#define MTOT (BATCH * SEQ)            // 4096 rows
#define OUT_ELEMS ((long long)BATCH * SEQ * D_MODEL)          // 4,194,304
#define ATTN_ELEMS ((long long)BATCH * NUM_HEADS * SEQ * SEQ) // 134,217,728

// Scratch (no allocations allowed) — 4 x 16 MB
__device__ float g_Q[MTOT * D_MODEL];
__device__ float g_K[MTOT * D_MODEL];
__device__ float g_V[MTOT * D_MODEL];
__device__ float g_ctx[MTOT * D_MODEL];

// ---------------------------------------------------------------------------
// Tiled fp32 GEMM: C[M,N] = A[M,K] @ W[K,N] + bias[N]
// 128x128 tile, TK=8, 256 threads, 8x8 accum per thread.
// ---------------------------------------------------------------------------
#define GTK 8
__global__ __launch_bounds__(256) void gemm_bias_kernel(
    const float* __restrict__ A, const float* __restrict__ W,
    const float* __restrict__ bias, float* __restrict__ C,
    int M, int N, int K)
{
    __shared__ float As[GTK][132];   // padded, stored transposed
    __shared__ float Bs[GTK][128];

    const int tid = threadIdx.x;
    const int bm = blockIdx.y * 128;
    const int bn = blockIdx.x * 128;
    const int tx = tid & 15;         // n direction
    const int ty = tid >> 4;         // m direction

    float acc[8][8];
#pragma unroll
    for (int i = 0; i < 8; i++)
#pragma unroll
        for (int j = 0; j < 8; j++) acc[i][j] = 0.f;

    const int ar = tid >> 1;              // 0..127 (A row within tile)
    const int akc = (tid & 1) * 4;        // 0 or 4 (A k offset)
    const int bkr = tid >> 5;             // 0..7   (B k row)
    const int bnc = (tid & 31) * 4;       // 0..124 (B n offset)

    for (int k0 = 0; k0 < K; k0 += GTK) {
        {
            float4 v = *reinterpret_cast<const float4*>(
                A + (size_t)(bm + ar) * K + k0 + akc);
            As[akc + 0][ar] = v.x;
            As[akc + 1][ar] = v.y;
            As[akc + 2][ar] = v.z;
            As[akc + 3][ar] = v.w;
        }
        {
            float4 v = *reinterpret_cast<const float4*>(
                W + (size_t)(k0 + bkr) * N + bn + bnc);
            *reinterpret_cast<float4*>(&Bs[bkr][bnc]) = v;
        }
        __syncthreads();

#pragma unroll
        for (int kk = 0; kk < GTK; kk++) {
            float a[8], b[8];
#pragma unroll
            for (int i = 0; i < 8; i++) a[i] = As[kk][ty * 8 + i];
#pragma unroll
            for (int j = 0; j < 8; j++) b[j] = Bs[kk][tx * 8 + j];
#pragma unroll
            for (int i = 0; i < 8; i++)
#pragma unroll
                for (int j = 0; j < 8; j++) acc[i][j] += a[i] * b[j];
        }
        __syncthreads();
    }

#pragma unroll
    for (int i = 0; i < 8; i++) {
        int m = bm + ty * 8 + i;
#pragma unroll
        for (int j = 0; j < 8; j += 4) {
            int n = bn + tx * 8 + j;
            float4 o;
            o.x = acc[i][j + 0] + bias[n + 0];
            o.y = acc[i][j + 1] + bias[n + 1];
            o.z = acc[i][j + 2] + bias[n + 2];
            o.w = acc[i][j + 3] + bias[n + 3];
            *reinterpret_cast<float4*>(C + (size_t)m * N + n) = o;
        }
    }
}

// ---------------------------------------------------------------------------
// Register-tiled causal attention. One block per (b, h, 64-row q-tile).
// 128 threads; each thread owns an 8x4 fragment of S / P / ctx.
// Writes unnormalized exp(logit) to attn, accumulates row sums in regs,
// rescales its own attn rows (and zeros the masked region) in an epilogue.
// ---------------------------------------------------------------------------
__global__ __launch_bounds__(128, 4) void attn_pass1(
    const float* __restrict__ Qp, const float* __restrict__ Kp,
    const float* __restrict__ Vp, float* __restrict__ attn,
    float* __restrict__ ctx)
{
    __shared__ float Qs[64][65];
    __shared__ float KVs[64][65];
    __shared__ float Ps[64][65];
    __shared__ float invs[64];

    const int tid   = threadIdx.x;
    const int qt    = (int)gridDim.x - 1 - (int)blockIdx.x;   // largest tile first
    const int h     = blockIdx.y & (NUM_HEADS - 1);
    const int b     = blockIdx.y >> 4;
    const int qbase = qt * 64;

    const int tx = tid & 15;
    const int ty = tid >> 4;            // 0..7
    const int r0 = ty * 8;
    const int n0 = tx * 4;

    const size_t qkvBase  = (size_t)b * SEQ * D_MODEL + (size_t)h * DEPTH;
    const size_t attnRow0 = (((size_t)b * NUM_HEADS + h) * SEQ + qbase) * SEQ;

    // Load Q tile [64 rows][64 d]
#pragma unroll
    for (int it = 0; it < 8; it++) {
        int idx = tid + it * 128;
        int r  = idx >> 4;
        int d4 = (idx & 15) * 4;
        float4 v = *reinterpret_cast<const float4*>(
            Qp + qkvBase + (size_t)(qbase + r) * D_MODEL + d4);
        Qs[r][d4 + 0] = v.x; Qs[r][d4 + 1] = v.y;
        Qs[r][d4 + 2] = v.z; Qs[r][d4 + 3] = v.w;
    }

    float ctxa[8][4];
    float rpart[8];
#pragma unroll
    for (int i = 0; i < 8; i++) {
        rpart[i] = 0.f;
#pragma unroll
        for (int j = 0; j < 4; j++) ctxa[i][j] = 0.f;
    }

    __syncthreads();

    for (int c = 0; c <= qt; c++) {
        const int kbase = c * 64;

        // Load K chunk [64 rows][64 d]
#pragma unroll
        for (int it = 0; it < 8; it++) {
            int idx = tid + it * 128;
            int r  = idx >> 4;
            int d4 = (idx & 15) * 4;
            float4 v = *reinterpret_cast<const float4*>(
                Kp + qkvBase + (size_t)(kbase + r) * D_MODEL + d4);
            KVs[r][d4 + 0] = v.x; KVs[r][d4 + 1] = v.y;
            KVs[r][d4 + 2] = v.z; KVs[r][d4 + 3] = v.w;
        }
        __syncthreads();

        // S = Q @ K^T  (8x4 fragment per thread)
        float s[8][4];
#pragma unroll
        for (int i = 0; i < 8; i++)
#pragma unroll
            for (int j = 0; j < 4; j++) s[i][j] = 0.f;

#pragma unroll 4
        for (int k = 0; k < 64; k++) {
            float a[8], bb[4];
#pragma unroll
            for (int i = 0; i < 8; i++) a[i] = Qs[r0 + i][k];
#pragma unroll
            for (int j = 0; j < 4; j++) bb[j] = KVs[n0 + j][k];
#pragma unroll
            for (int i = 0; i < 8; i++)
#pragma unroll
                for (int j = 0; j < 4; j++) s[i][j] += a[i] * bb[j];
        }

        // P = exp(S/8) with causal mask on the diagonal tile.
        const bool diag = (c == qt);
#pragma unroll
        for (int i = 0; i < 8; i++) {
            float p[4];
#pragma unroll
            for (int j = 0; j < 4; j++) {
                float e = __expf(s[i][j] * 0.125f);
                if (diag && (n0 + j) > (r0 + i)) e = 0.f;
                p[j] = e;
                rpart[i] += e;
                Ps[r0 + i][n0 + j] = e;
            }
            if (attn) {
                float4 pv; pv.x = p[0]; pv.y = p[1]; pv.z = p[2]; pv.w = p[3];
                *reinterpret_cast<float4*>(
                    attn + attnRow0 + (size_t)(r0 + i) * SEQ + kbase + n0) = pv;
            }
        }
        __syncthreads();   // done reading K, Ps fully written

        // Load V chunk [64 k][64 d]
#pragma unroll
        for (int it = 0; it < 8; it++) {
            int idx = tid + it * 128;
            int r  = idx >> 4;
            int d4 = (idx & 15) * 4;
            float4 v = *reinterpret_cast<const float4*>(
                Vp + qkvBase + (size_t)(kbase + r) * D_MODEL + d4);
            KVs[r][d4 + 0] = v.x; KVs[r][d4 + 1] = v.y;
            KVs[r][d4 + 2] = v.z; KVs[r][d4 + 3] = v.w;
        }
        __syncthreads();

        // ctx += P @ V
#pragma unroll 4
        for (int k = 0; k < 64; k++) {
            float a[8], bb[4];
#pragma unroll
            for (int i = 0; i < 8; i++) a[i] = Ps[r0 + i][k];
#pragma unroll
            for (int j = 0; j < 4; j++) bb[j] = KVs[k][n0 + j];
#pragma unroll
            for (int i = 0; i < 8; i++)
#pragma unroll
                for (int j = 0; j < 4; j++) ctxa[i][j] += a[i] * bb[j];
        }
        __syncthreads();   // before KVs/Ps reuse next chunk
    }

    // Reduce row sums across the 16 thread-columns (reuse Ps)
#pragma unroll
    for (int i = 0; i < 8; i++) Ps[r0 + i][tx] = rpart[i];
    __syncthreads();
    if (tid < 64) {
        float sm = 0.f;
#pragma unroll
        for (int x = 0; x < 16; x++) sm += Ps[tid][x];
        invs[tid] = 1.0f / sm;
    }
    __syncthreads();

    // Write normalized ctx: ctx[b, q, h*64 + d]
#pragma unroll
    for (int i = 0; i < 8; i++) {
        float inv = invs[r0 + i];
        float4 v;
        v.x = ctxa[i][0] * inv; v.y = ctxa[i][1] * inv;
        v.z = ctxa[i][2] * inv; v.w = ctxa[i][3] * inv;
        *reinterpret_cast<float4*>(
            ctx + qkvBase + (size_t)(qbase + r0 + i) * D_MODEL + n0) = v;
    }

    // Epilogue: rescale this block's attn rows; zero the masked region.
    if (attn) {
        for (int c = 0; c < SEQ / 64; c++) {
            const int kbase = c * 64;
            if (c <= qt) {
#pragma unroll
                for (int it = 0; it < 8; it++) {
                    int idx = tid + it * 128;
                    int r  = idx >> 4;
                    int d4 = (idx & 15) * 4;
                    float inv = invs[r];
                    float4* p = reinterpret_cast<float4*>(
                        attn + attnRow0 + (size_t)r * SEQ + kbase + d4);
                    float4 v = *p;
                    v.x *= inv; v.y *= inv; v.z *= inv; v.w *= inv;
                    *p = v;
                }
            } else {
                const float4 z = {0.f, 0.f, 0.f, 0.f};
#pragma unroll
                for (int it = 0; it < 8; it++) {
                    int idx = tid + it * 128;
                    int r  = idx >> 4;
                    int d4 = (idx & 15) * 4;
                    *reinterpret_cast<float4*>(
                        attn + attnRow0 + (size_t)r * SEQ + kbase + d4) = z;
                }
            }
        }
    }
}

// ---------------------------------------------------------------------------
extern "C" void kernel_launch(void* const* d_in, const int* in_sizes, int n_in,
                              void* d_out, int out_size)
{
    const float* q  = (const float*)d_in[0];
    const float* k  = (const float*)d_in[1];
    const float* v  = (const float*)d_in[2];
    // d_in[3] is the mask — causal structure applied analytically.
    const float* wq = (const float*)d_in[4];
    const float* bq = (const float*)d_in[5];
    const float* wk = (const float*)d_in[6];
    const float* bk = (const float*)d_in[7];
    const float* wv = (const float*)d_in[8];
    const float* bv = (const float*)d_in[9];
    const float* wo = (const float*)d_in[10];
    const float* bo = (const float*)d_in[11];

    float* out = (float*)d_out;
    float* attn = nullptr;
    if ((long long)out_size >= OUT_ELEMS + ATTN_ELEMS) {
        attn = out + OUT_ELEMS;
    }

    float *Qs, *Ks, *Vs, *Cs;
    cudaGetSymbolAddress((void**)&Qs, g_Q);
    cudaGetSymbolAddress((void**)&Ks, g_K);
    cudaGetSymbolAddress((void**)&Vs, g_V);
    cudaGetSymbolAddress((void**)&Cs, g_ctx);

    dim3 ggrid(D_MODEL / 128, MTOT / 128);   // (8, 32)
    gemm_bias_kernel<<<ggrid, 256>>>(q, wq, bq, Qs, MTOT, D_MODEL, D_MODEL);
    gemm_bias_kernel<<<ggrid, 256>>>(k, wk, bk, Ks, MTOT, D_MODEL, D_MODEL);
    gemm_bias_kernel<<<ggrid, 256>>>(v, wv, bv, Vs, MTOT, D_MODEL, D_MODEL);

    attn_pass1<<<dim3(SEQ / 64, BATCH * NUM_HEADS), 128>>>(Qs, Ks, Vs, attn, Cs);

    gemm_bias_kernel<<<ggrid, 256>>>(Cs, wo, bo, out, MTOT, D_MODEL, D_MODEL);
}

// round 6
// speedup vs baseline: 3.5850x; 1.0039x over previous
#include <cuda_runtime.h>
#include <cstdint>

#define D_MODEL 1024
#define NUM_HEADS 16
#define DEPTH 64
#define BATCH 2
#define SEQ 2048
#define MTOT (BATCH * SEQ)            // 4096 rows
#define OUT_ELEMS ((long long)BATCH * SEQ * D_MODEL)          // 4,194,304
#define ATTN_ELEMS ((long long)BATCH * NUM_HEADS * SEQ * SEQ) // 134,217,728

// Scratch (no allocations allowed) — 4 x 16 MB
__device__ float g_Q[MTOT * D_MODEL];
__device__ float g_K[MTOT * D_MODEL];
__device__ float g_V[MTOT * D_MODEL];
__device__ float g_ctx[MTOT * D_MODEL];

// ---------------------------------------------------------------------------
// Tiled fp32 GEMM: C[M,N] = A[M,K] @ W[K,N] + bias[N]
// 128x128 tile, TK=8, 256 threads, 8x8 accum per thread.
// ---------------------------------------------------------------------------
#define GTK 8
__global__ __launch_bounds__(256) void gemm_bias_kernel(
    const float* __restrict__ A, const float* __restrict__ W,
    const float* __restrict__ bias, float* __restrict__ C,
    int M, int N, int K)
{
    __shared__ float As[GTK][132];   // padded, stored transposed
    __shared__ float Bs[GTK][128];

    const int tid = threadIdx.x;
    const int bm = blockIdx.y * 128;
    const int bn = blockIdx.x * 128;
    const int tx = tid & 15;         // n direction
    const int ty = tid >> 4;         // m direction

    float acc[8][8];
#pragma unroll
    for (int i = 0; i < 8; i++)
#pragma unroll
        for (int j = 0; j < 8; j++) acc[i][j] = 0.f;

    const int ar = tid >> 1;              // 0..127 (A row within tile)
    const int akc = (tid & 1) * 4;        // 0 or 4 (A k offset)
    const int bkr = tid >> 5;             // 0..7   (B k row)
    const int bnc = (tid & 31) * 4;       // 0..124 (B n offset)

    for (int k0 = 0; k0 < K; k0 += GTK) {
        {
            float4 v = *reinterpret_cast<const float4*>(
                A + (size_t)(bm + ar) * K + k0 + akc);
            As[akc + 0][ar] = v.x;
            As[akc + 1][ar] = v.y;
            As[akc + 2][ar] = v.z;
            As[akc + 3][ar] = v.w;
        }
        {
            float4 v = *reinterpret_cast<const float4*>(
                W + (size_t)(k0 + bkr) * N + bn + bnc);
            *reinterpret_cast<float4*>(&Bs[bkr][bnc]) = v;
        }
        __syncthreads();

#pragma unroll
        for (int kk = 0; kk < GTK; kk++) {
            float a[8], b[8];
#pragma unroll
            for (int i = 0; i < 8; i++) a[i] = As[kk][ty * 8 + i];
#pragma unroll
            for (int j = 0; j < 8; j++) b[j] = Bs[kk][tx * 8 + j];
#pragma unroll
            for (int i = 0; i < 8; i++)
#pragma unroll
                for (int j = 0; j < 8; j++) acc[i][j] += a[i] * b[j];
        }
        __syncthreads();
    }

#pragma unroll
    for (int i = 0; i < 8; i++) {
        int m = bm + ty * 8 + i;
#pragma unroll
        for (int j = 0; j < 8; j += 4) {
            int n = bn + tx * 8 + j;
            float4 o;
            o.x = acc[i][j + 0] + bias[n + 0];
            o.y = acc[i][j + 1] + bias[n + 1];
            o.z = acc[i][j + 2] + bias[n + 2];
            o.w = acc[i][j + 3] + bias[n + 3];
            *reinterpret_cast<float4*>(C + (size_t)m * N + n) = o;
        }
    }
}

// ---------------------------------------------------------------------------
// Register-tiled causal attention. One block per (b, h, 64-row q-tile).
// 128 threads; each thread owns an 8x4 fragment of S / P / ctx.
// Writes unnormalized exp(logit) to attn, accumulates row sums in regs,
// rescales its own attn rows (and zeros the masked region) in an epilogue.
// ---------------------------------------------------------------------------
__global__ __launch_bounds__(128, 4) void attn_pass1(
    const float* __restrict__ Qp, const float* __restrict__ Kp,
    const float* __restrict__ Vp, float* __restrict__ attn,
    float* __restrict__ ctx)
{
    __shared__ float Qs[64][65];
    __shared__ float KVs[64][65];
    __shared__ float Ps[64][65];
    __shared__ float invs[64];

    const int tid   = threadIdx.x;
    const int qt    = (int)gridDim.x - 1 - (int)blockIdx.x;   // largest tile first
    const int h     = blockIdx.y & (NUM_HEADS - 1);
    const int b     = blockIdx.y >> 4;
    const int qbase = qt * 64;

    const int tx = tid & 15;
    const int ty = tid >> 4;            // 0..7
    const int r0 = ty * 8;
    const int n0 = tx * 4;

    const size_t qkvBase  = (size_t)b * SEQ * D_MODEL + (size_t)h * DEPTH;
    const size_t attnRow0 = (((size_t)b * NUM_HEADS + h) * SEQ + qbase) * SEQ;

    // Load Q tile [64 rows][64 d]
#pragma unroll
    for (int it = 0; it < 8; it++) {
        int idx = tid + it * 128;
        int r  = idx >> 4;
        int d4 = (idx & 15) * 4;
        float4 v = *reinterpret_cast<const float4*>(
            Qp + qkvBase + (size_t)(qbase + r) * D_MODEL + d4);
        Qs[r][d4 + 0] = v.x; Qs[r][d4 + 1] = v.y;
        Qs[r][d4 + 2] = v.z; Qs[r][d4 + 3] = v.w;
    }

    float ctxa[8][4];
    float rpart[8];
#pragma unroll
    for (int i = 0; i < 8; i++) {
        rpart[i] = 0.f;
#pragma unroll
        for (int j = 0; j < 4; j++) ctxa[i][j] = 0.f;
    }

    __syncthreads();

    for (int c = 0; c <= qt; c++) {
        const int kbase = c * 64;

        // Load K chunk [64 rows][64 d]
#pragma unroll
        for (int it = 0; it < 8; it++) {
            int idx = tid + it * 128;
            int r  = idx >> 4;
            int d4 = (idx & 15) * 4;
            float4 v = *reinterpret_cast<const float4*>(
                Kp + qkvBase + (size_t)(kbase + r) * D_MODEL + d4);
            KVs[r][d4 + 0] = v.x; KVs[r][d4 + 1] = v.y;
            KVs[r][d4 + 2] = v.z; KVs[r][d4 + 3] = v.w;
        }
        __syncthreads();

        // S = Q @ K^T  (8x4 fragment per thread)
        float s[8][4];
#pragma unroll
        for (int i = 0; i < 8; i++)
#pragma unroll
            for (int j = 0; j < 4; j++) s[i][j] = 0.f;

#pragma unroll 4
        for (int k = 0; k < 64; k++) {
            float a[8], bb[4];
#pragma unroll
            for (int i = 0; i < 8; i++) a[i] = Qs[r0 + i][k];
#pragma unroll
            for (int j = 0; j < 4; j++) bb[j] = KVs[n0 + j][k];
#pragma unroll
            for (int i = 0; i < 8; i++)
#pragma unroll
                for (int j = 0; j < 4; j++) s[i][j] += a[i] * bb[j];
        }

        // P = exp(S/8) with causal mask on the diagonal tile.
        const bool diag = (c == qt);
#pragma unroll
        for (int i = 0; i < 8; i++) {
            float p[4];
#pragma unroll
            for (int j = 0; j < 4; j++) {
                float e = __expf(s[i][j] * 0.125f);
                if (diag && (n0 + j) > (r0 + i)) e = 0.f;
                p[j] = e;
                rpart[i] += e;
                Ps[r0 + i][n0 + j] = e;
            }
            if (attn) {
                float4 pv; pv.x = p[0]; pv.y = p[1]; pv.z = p[2]; pv.w = p[3];
                *reinterpret_cast<float4*>(
                    attn + attnRow0 + (size_t)(r0 + i) * SEQ + kbase + n0) = pv;
            }
        }
        __syncthreads();   // done reading K, Ps fully written

        // Load V chunk [64 k][64 d]
#pragma unroll
        for (int it = 0; it < 8; it++) {
            int idx = tid + it * 128;
            int r  = idx >> 4;
            int d4 = (idx & 15) * 4;
            float4 v = *reinterpret_cast<const float4*>(
                Vp + qkvBase + (size_t)(kbase + r) * D_MODEL + d4);
            KVs[r][d4 + 0] = v.x; KVs[r][d4 + 1] = v.y;
            KVs[r][d4 + 2] = v.z; KVs[r][d4 + 3] = v.w;
        }
        __syncthreads();

        // ctx += P @ V
#pragma unroll 4
        for (int k = 0; k < 64; k++) {
            float a[8], bb[4];
#pragma unroll
            for (int i = 0; i < 8; i++) a[i] = Ps[r0 + i][k];
#pragma unroll
            for (int j = 0; j < 4; j++) bb[j] = KVs[k][n0 + j];
#pragma unroll
            for (int i = 0; i < 8; i++)
#pragma unroll
                for (int j = 0; j < 4; j++) ctxa[i][j] += a[i] * bb[j];
        }
        __syncthreads();   // before KVs/Ps reuse next chunk
    }

    // Reduce row sums across the 16 thread-columns (reuse Ps)
#pragma unroll
    for (int i = 0; i < 8; i++) Ps[r0 + i][tx] = rpart[i];
    __syncthreads();
    if (tid < 64) {
        float sm = 0.f;
#pragma unroll
        for (int x = 0; x < 16; x++) sm += Ps[tid][x];
        invs[tid] = 1.0f / sm;
    }
    __syncthreads();

    // Write normalized ctx: ctx[b, q, h*64 + d]
#pragma unroll
    for (int i = 0; i < 8; i++) {
        float inv = invs[r0 + i];
        float4 v;
        v.x = ctxa[i][0] * inv; v.y = ctxa[i][1] * inv;
        v.z = ctxa[i][2] * inv; v.w = ctxa[i][3] * inv;
        *reinterpret_cast<float4*>(
            ctx + qkvBase + (size_t)(qbase + r0 + i) * D_MODEL + n0) = v;
    }

    // Epilogue: rescale this block's attn rows; zero the masked region.
    if (attn) {
        for (int c = 0; c < SEQ / 64; c++) {
            const int kbase = c * 64;
            if (c <= qt) {
#pragma unroll
                for (int it = 0; it < 8; it++) {
                    int idx = tid + it * 128;
                    int r  = idx >> 4;
                    int d4 = (idx & 15) * 4;
                    float inv = invs[r];
                    float4* p = reinterpret_cast<float4*>(
                        attn + attnRow0 + (size_t)r * SEQ + kbase + d4);
                    float4 v = *p;
                    v.x *= inv; v.y *= inv; v.z *= inv; v.w *= inv;
                    *p = v;
                }
            } else {
                const float4 z = {0.f, 0.f, 0.f, 0.f};
#pragma unroll
                for (int it = 0; it < 8; it++) {
                    int idx = tid + it * 128;
                    int r  = idx >> 4;
                    int d4 = (idx & 15) * 4;
                    *reinterpret_cast<float4*>(
                        attn + attnRow0 + (size_t)r * SEQ + kbase + d4) = z;
                }
            }
        }
    }
}

// ---------------------------------------------------------------------------
extern "C" void kernel_launch(void* const* d_in, const int* in_sizes, int n_in,
                              void* d_out, int out_size)
{
    const float* q  = (const float*)d_in[0];
    const float* k  = (const float*)d_in[1];
    const float* v  = (const float*)d_in[2];
    // d_in[3] is the mask — causal structure applied analytically.
    const float* wq = (const float*)d_in[4];
    const float* bq = (const float*)d_in[5];
    const float* wk = (const float*)d_in[6];
    const float* bk = (const float*)d_in[7];
    const float* wv = (const float*)d_in[8];
    const float* bv = (const float*)d_in[9];
    const float* wo = (const float*)d_in[10];
    const float* bo = (const float*)d_in[11];

    float* out = (float*)d_out;
    float* attn = nullptr;
    if ((long long)out_size >= OUT_ELEMS + ATTN_ELEMS) {
        attn = out + OUT_ELEMS;
    }

    float *Qs, *Ks, *Vs, *Cs;
    cudaGetSymbolAddress((void**)&Qs, g_Q);
    cudaGetSymbolAddress((void**)&Ks, g_K);
    cudaGetSymbolAddress((void**)&Vs, g_V);
    cudaGetSymbolAddress((void**)&Cs, g_ctx);

    dim3 ggrid(D_MODEL / 128, MTOT / 128);   // (8, 32)
    gemm_bias_kernel<<<ggrid, 256>>>(q, wq, bq, Qs, MTOT, D_MODEL, D_MODEL);
    gemm_bias_kernel<<<ggrid, 256>>>(k, wk, bk, Ks, MTOT, D_MODEL, D_MODEL);
    gemm_bias_kernel<<<ggrid, 256>>>(v, wv, bv, Vs, MTOT, D_MODEL, D_MODEL);

    attn_pass1<<<dim3(SEQ / 64, BATCH * NUM_HEADS), 128>>>(Qs, Ks, Vs, attn, Cs);

    gemm_bias_kernel<<<ggrid, 256>>>(Cs, wo, bo, out, MTOT, D_MODEL, D_MODEL);
}